// round 12
// baseline (speedup 1.0000x reference)
#include <cuda_runtime.h>
#include <cuda_bf16.h>
#include <cstdint>

// ---------------- problem dims ----------------
#define TT 1024
#define BB 8
#define DD 1024
#define HH 16
#define ROWS 8192
#define SEGC 8388608u
#define KC 3072                 // concatenated split-bf16 K (hi|hi|lo vs hi|lo|hi)

typedef unsigned long long ull;

// ---------------- device scratch ----------------
__device__ float g_proj[5ull * SEGC];     // q,k,v,apre,bpre (fp32)
__device__ float g_alpha[ROWS * HH];
__device__ float g_beta[ROWS * HH];
__device__ __align__(16) __nv_bfloat16 g_xcat[(size_t)ROWS * KC];   // 48 MB
__device__ __align__(16) __nv_bfloat16 g_wcat[(size_t)5120 * KC];   // 30 MB

// ---------------- helpers ----------------
__device__ __forceinline__ uint32_t smem_u32(const void* p) {
    uint32_t a;
    asm("{ .reg .u64 t; cvta.to.shared.u64 t, %1; cvt.u32.u64 %0, t; }" : "=r"(a) : "l"(p));
    return a;
}
__device__ __forceinline__ void cpa16(uint32_t dst, const void* src) {
    asm volatile("cp.async.cg.shared.global [%0], [%1], 16;" :: "r"(dst), "l"(src));
}
#define CP_COMMIT() asm volatile("cp.async.commit_group;")
#define CP_WAIT1()  asm volatile("cp.async.wait_group 1;")

__device__ __forceinline__ void ldm4(uint32_t* r, uint32_t a) {
    asm volatile("ldmatrix.sync.aligned.m8n8.x4.shared.b16 {%0,%1,%2,%3}, [%4];"
        : "=r"(r[0]), "=r"(r[1]), "=r"(r[2]), "=r"(r[3]) : "r"(a));
}
__device__ __forceinline__ void mma16816(float* d, const uint32_t* a, uint32_t b0, uint32_t b1) {
    asm volatile(
        "mma.sync.aligned.m16n8k16.row.col.f32.bf16.bf16.f32 "
        "{%0,%1,%2,%3},{%4,%5,%6,%7},{%8,%9},{%0,%1,%2,%3};"
        : "+f"(d[0]), "+f"(d[1]), "+f"(d[2]), "+f"(d[3])
        : "r"(a[0]), "r"(a[1]), "r"(a[2]), "r"(a[3]), "r"(b0), "r"(b1));
}

// packed f32x2 (sm_100+ FFMA2)
#define FMA2(d, a, b, c) asm("fma.rn.f32x2 %0, %1, %2, %3;" : "=l"(d) : "l"(a), "l"(b), "l"(c))
#define MUL2(d, a, b)    asm("mul.rn.f32x2 %0, %1, %2;"     : "=l"(d) : "l"(a), "l"(b))
#define PK2(d, x, y)     asm("mov.b64 %0, {%1, %2};"        : "=l"(d) : "f"(x), "f"(y))
#define UNPK2(x, y, d)   asm("mov.b64 {%0, %1}, %2;"        : "=f"(x), "=f"(y) : "l"(d))

// split one float into bf16 hi + bf16 lo
__device__ __forceinline__ void split2(float f0, float f1, uint32_t& hw, uint32_t& lw) {
    __nv_bfloat16 h0 = __float2bfloat16(f0);
    __nv_bfloat16 h1 = __float2bfloat16(f1);
    __nv_bfloat16 l0 = __float2bfloat16(f0 - __bfloat162float(h0));
    __nv_bfloat16 l1 = __float2bfloat16(f1 - __bfloat162float(h1));
    hw = (uint32_t)__bfloat16_as_ushort(h0) | ((uint32_t)__bfloat16_as_ushort(h1) << 16);
    lw = (uint32_t)__bfloat16_as_ushort(l0) | ((uint32_t)__bfloat16_as_ushort(l1) << 16);
}

// dummy launches to place the ncu capture slot (4th launch) on gemm_mma
__global__ void knop() {}

// =====================================================================
// pack_all: fused pack_x + pack_w (unchanged).
// =====================================================================
__global__ __launch_bounds__(256)
void pack_all(const float* __restrict__ x,
              const float* __restrict__ W0, const float* __restrict__ W1,
              const float* __restrict__ W2, const float* __restrict__ W3,
              const float* __restrict__ W4)
{
    unsigned idx = blockIdx.x * 256 + threadIdx.x;
    if (idx < 1048576u) {
        unsigned e = idx * 8;
        unsigned row = e >> 10, col = e & 1023;
        float4 f0 = *(const float4*)(x + e);
        float4 f1 = *(const float4*)(x + e + 4);
        uint4 hi, lo;
        split2(f0.x, f0.y, hi.x, lo.x);
        split2(f0.z, f0.w, hi.y, lo.y);
        split2(f1.x, f1.y, hi.z, lo.z);
        split2(f1.z, f1.w, hi.w, lo.w);
        __nv_bfloat16* base = g_xcat + (size_t)row * KC;
        *(uint4*)(base + col)        = hi;
        *(uint4*)(base + col + 1024) = hi;
        *(uint4*)(base + col + 2048) = lo;
    } else {
        unsigned j = idx - 1048576u;
        unsigned e = j * 8;
        unsigned seg = e >> 20;
        unsigned n = (e >> 10) & 1023, k = e & 1023;
        const float* W = (seg == 0) ? W0 : (seg == 1) ? W1 : (seg == 2) ? W2
                         : (seg == 3) ? W3 : W4;
        const float* src = W + (size_t)n * 1024 + k;
        float4 f0 = *(const float4*)(src);
        float4 f1 = *(const float4*)(src + 4);
        uint4 hi, lo;
        split2(f0.x, f0.y, hi.x, lo.x);
        split2(f0.z, f0.w, hi.y, lo.y);
        split2(f1.x, f1.y, hi.z, lo.z);
        split2(f1.z, f1.w, hi.w, lo.w);
        __nv_bfloat16* base = g_wcat + (size_t)(seg * 1024 + n) * KC;
        *(uint4*)(base + k)        = hi;
        *(uint4*)(base + k + 1024) = lo;
        *(uint4*)(base + k + 2048) = hi;
    }
}

// =====================================================================
// gemm_mma v2: BM=BN=128, BK=32, 4 warps (2m x 2n), warp tile 64x64,
// 3-stage cp.async ring (2 in flight), 3 CTAs/SM (12 warps/SM).
// B-frags resident per kstep (16 regs); A-frags streamed per f (4 regs)
// to stay under the 170-reg cap. 80B-padded rows, conflict-free ldmatrix.
// =====================================================================
#define STG 20480               // bytes/stage: A 128*80 + B 128*80

__global__ __launch_bounds__(128, 3)
void gemm_mma()
{
    extern __shared__ __align__(16) unsigned char sm[];
    const uint32_t smb = smem_u32(sm);

    const int bid = blockIdx.x;
    const int mt = bid / 40, nt = bid % 40;
    const int tid = threadIdx.x;
    const int lane = tid & 31, wid = tid >> 5;
    const int wm = wid & 1, wn = wid >> 1;

    // global->smem: 128 threads x 16B, 4 row-passes per operand
    const int lrow = tid >> 2, lch = tid & 3;     // lrow 0..31
    const __nv_bfloat16* Ag = g_xcat + (size_t)(mt * 128 + lrow) * KC + lch * 8;
    const __nv_bfloat16* Bg = g_wcat + (size_t)(nt * 128 + lrow) * KC + lch * 8;
    const uint32_t sA = smb + lrow * 80 + lch * 16;
    const uint32_t sB = smb + 10240 + lrow * 80 + lch * 16;

    auto load = [&](int it, int stage) {
        const uint32_t off = stage * STG;
        const __nv_bfloat16* ag = Ag + it * 32;
        const __nv_bfloat16* bg = Bg + it * 32;
#pragma unroll
        for (int p = 0; p < 4; p++) {
            cpa16(sA + off + p * (32 * 80), ag + (size_t)(p * 32) * KC);
            cpa16(sB + off + p * (32 * 80), bg + (size_t)(p * 32) * KC);
        }
    };

    // ldmatrix base addresses (stage 0, kstep 0)
    const uint32_t c16 = (lane >> 4) * 16;
    const uint32_t aBase = smb + (wm * 64 + (lane & 15)) * 80 + c16;
    const uint32_t bBase = smb + 10240 + (wn * 64 + (lane & 15)) * 80 + c16;

    float acc[4][8][4];
#pragma unroll
    for (int f = 0; f < 4; f++)
#pragma unroll
        for (int g = 0; g < 8; g++)
#pragma unroll
            for (int i = 0; i < 4; i++) acc[f][g][i] = 0.f;

    // prologue: 2 stages in flight
    load(0, 0); CP_COMMIT();
    load(1, 1); CP_COMMIT();

    const int NIT = KC / 32;    // 96
    int stage = 0;
    for (int it = 0; it < NIT; it++) {
        CP_WAIT1();             // 2 pending -> oldest (stage) complete
        __syncthreads();
        if (it + 2 < NIT) {
            int ns = stage + 2; if (ns >= 3) ns -= 3;
            load(it + 2, ns);
        }
        CP_COMMIT();

        const uint32_t st = stage * STG;
#pragma unroll
        for (int ks = 0; ks < 2; ks++) {
            uint32_t bf[4][4];
#pragma unroll
            for (int x = 0; x < 4; x++) ldm4(bf[x], bBase + st + x * (16 * 80) + ks * 32);
#pragma unroll
            for (int f = 0; f < 4; f++) {
                uint32_t af[4];
                ldm4(af, aBase + st + f * (16 * 80) + ks * 32);
#pragma unroll
                for (int g = 0; g < 8; g++) {
                    const uint32_t b0 = bf[g >> 1][g & 1];
                    const uint32_t b1 = bf[g >> 1][(g & 1) + 2];
                    mma16816(acc[f][g], af, b0, b1);
                }
            }
        }
        stage++; if (stage == 3) stage = 0;
    }

    // epilogue: direct fp32 stores to g_proj (seg, 8192, 1024)
    const int seg = nt >> 3;
    float* op = g_proj + (size_t)seg * SEGC;
    const int rbase = mt * 128 + wm * 64 + (lane >> 2);
    const int cbase = (nt & 7) * 128 + wn * 64 + (lane & 3) * 2;
#pragma unroll
    for (int f = 0; f < 4; f++) {
#pragma unroll
        for (int g = 0; g < 8; g++) {
            const int r = rbase + f * 16;
            const int c = cbase + g * 8;
            float2 v0 = make_float2(acc[f][g][0], acc[f][g][1]);
            float2 v1 = make_float2(acc[f][g][2], acc[f][g][3]);
            *(float2*)(op + (size_t)r * 1024 + c)       = v0;
            *(float2*)(op + (size_t)(r + 8) * 1024 + c) = v1;
        }
    }
}

// =====================================================================
// postproc: unchanged.
// =====================================================================
__device__ __forceinline__ float sigf(float x) { return 1.0f / (1.0f + expf(-x)); }

__global__ __launch_bounds__(256)
void postproc(const float* __restrict__ b_alpha, const float* __restrict__ b_beta)
{
    const int wid = threadIdx.x >> 5;
    const int lane = threadIdx.x & 31;
    const int gb = blockIdx.x * 8 + wid;   // tb*16 + h
    const int h = gb & 15;
    const size_t row = (size_t)(gb >> 4) * DD + h * 64 + lane * 2;

    float2 q  = *(float2*)(g_proj + row);
    float2 k  = *(float2*)(g_proj + (size_t)SEGC + row);
    float2 ap = *(float2*)(g_proj + 3ull * SEGC + row);
    float2 bp = *(float2*)(g_proj + 4ull * SEGC + row);
    float2 ba = *(const float2*)(b_alpha + h * 64 + lane * 2);
    float2 bbv = *(const float2*)(b_beta + h * 64 + lane * 2);

    float sq = fmaf(q.x, q.x, q.y * q.y);
    float sk = fmaf(k.x, k.x, k.y * k.y);
    float sa = sigf(ap.x + ba.x) + sigf(ap.y + ba.y);
    float sb = sigf(bp.x + bbv.x) + sigf(bp.y + bbv.y);
#pragma unroll
    for (int m = 16; m; m >>= 1) {
        sq += __shfl_xor_sync(0xffffffffu, sq, m);
        sk += __shfl_xor_sync(0xffffffffu, sk, m);
        sa += __shfl_xor_sync(0xffffffffu, sa, m);
        sb += __shfl_xor_sync(0xffffffffu, sb, m);
    }
    const float qi = 1.0f / fmaxf(sqrtf(sq), 1e-12f);
    const float ki = 1.0f / fmaxf(sqrtf(sk), 1e-12f);
    q.x *= qi; q.y *= qi;
    k.x *= ki; k.y *= ki;
    *(float2*)(g_proj + row) = q;
    *(float2*)(g_proj + (size_t)SEGC + row) = k;
    if (lane == 0) {
        g_alpha[gb] = sa * (1.0f / 64.0f);
        g_beta[gb]  = sb * (1.0f / 64.0f);
    }
}

// =====================================================================
// scan: EXACT R8 v2 (best measured ~365us residual).
// 128 blocks x 256 threads = 64 rows x 4 col-quarters; register-resident
// 4-slot prefetch; packed f32x2 arithmetic.
// =====================================================================
#define LOADS(S, t) { \
    const float4* kp = (const float4*)(kb + (size_t)(t) * 8192) + (qu * 4); \
    kr##S##_0 = kp[0]; kr##S##_1 = kp[1]; kr##S##_2 = kp[2]; kr##S##_3 = kp[3]; \
    const float4* qp = (const float4*)(qb + (size_t)(t) * 8192) + (qu * 4); \
    qr##S##_0 = qp[0]; qr##S##_1 = qp[1]; qr##S##_2 = qp[2]; qr##S##_3 = qp[3]; \
    vr##S = vb[(size_t)(t) * 8192 + d]; \
    ar##S = g_alpha[(t) * 128 + bh]; \
    br##S = g_beta[(t) * 128 + bh]; }

#define STEP(S, tt) { \
    const float a = ar##S, be = br##S, vv = vr##S; \
    ull K0,K1,K2,K3,K4,K5,K6,K7, Q0,Q1,Q2,Q3,Q4,Q5,Q6,Q7; \
    PK2(K0, kr##S##_0.x, kr##S##_0.y); PK2(K1, kr##S##_0.z, kr##S##_0.w); \
    PK2(K2, kr##S##_1.x, kr##S##_1.y); PK2(K3, kr##S##_1.z, kr##S##_1.w); \
    PK2(K4, kr##S##_2.x, kr##S##_2.y); PK2(K5, kr##S##_2.z, kr##S##_2.w); \
    PK2(K6, kr##S##_3.x, kr##S##_3.y); PK2(K7, kr##S##_3.z, kr##S##_3.w); \
    PK2(Q0, qr##S##_0.x, qr##S##_0.y); PK2(Q1, qr##S##_0.z, qr##S##_0.w); \
    PK2(Q2, qr##S##_1.x, qr##S##_1.y); PK2(Q3, qr##S##_1.z, qr##S##_1.w); \
    PK2(Q4, qr##S##_2.x, qr##S##_2.y); PK2(Q5, qr##S##_2.z, qr##S##_2.w); \
    PK2(Q6, qr##S##_3.x, qr##S##_3.y); PK2(Q7, qr##S##_3.z, qr##S##_3.w); \
    ull d0, d1; \
    MUL2(d0, s_0, K0); MUL2(d1, s_1, K1); \
    FMA2(d0, s_2, K2, d0); FMA2(d1, s_3, K3, d1); \
    FMA2(d0, s_4, K4, d0); FMA2(d1, s_5, K5, d1); \
    FMA2(d0, s_6, K6, d0); FMA2(d1, s_7, K7, d1); \
    float dx, dy, ex, ey; UNPK2(dx, dy, d0); UNPK2(ex, ey, d1); \
    float sk = (dx + ex) + (dy + ey); \
    sk += __shfl_xor_sync(0xffffffffu, sk, 1); \
    sk += __shfl_xor_sync(0xffffffffu, sk, 2); \
    const float coef = be * fmaf(-a, sk, vv); \
    ull a2, c2; PK2(a2, a, a); PK2(c2, coef, coef); \
    ull o0, o1, tmp; \
    MUL2(tmp, a2, s_0); FMA2(s_0, c2, K0, tmp); MUL2(o0, s_0, Q0); \
    MUL2(tmp, a2, s_1); FMA2(s_1, c2, K1, tmp); MUL2(o1, s_1, Q1); \
    MUL2(tmp, a2, s_2); FMA2(s_2, c2, K2, tmp); FMA2(o0, s_2, Q2, o0); \
    MUL2(tmp, a2, s_3); FMA2(s_3, c2, K3, tmp); FMA2(o1, s_3, Q3, o1); \
    MUL2(tmp, a2, s_4); FMA2(s_4, c2, K4, tmp); FMA2(o0, s_4, Q4, o0); \
    MUL2(tmp, a2, s_5); FMA2(s_5, c2, K5, tmp); FMA2(o1, s_5, Q5, o1); \
    MUL2(tmp, a2, s_6); FMA2(s_6, c2, K6, tmp); FMA2(o0, s_6, Q6, o0); \
    MUL2(tmp, a2, s_7); FMA2(s_7, c2, K7, tmp); FMA2(o1, s_7, Q7, o1); \
    float ox, oy, px, py; UNPK2(ox, oy, o0); UNPK2(px, py, o1); \
    float oo = (ox + px) + (oy + py); \
    oo += __shfl_xor_sync(0xffffffffu, oo, 1); \
    oo += __shfl_xor_sync(0xffffffffu, oo, 2); \
    if (qu == 0) out[(size_t)(tt) * 8192 + ob] = oo; \
    if ((tt) + 4 < TT) LOADS(S, (tt) + 4); }

__global__ __launch_bounds__(256, 1)
void scan(const float* __restrict__ S0, float* __restrict__ out)
{
    const int bh = blockIdx.x;
    const int b = bh >> 4, h = bh & 15;
    const int tid = threadIdx.x;
    const int d = tid >> 2, qu = tid & 3;

    const float4* Sp = (const float4*)(S0 + ((size_t)bh * 64 + d) * 64 + qu * 16);
    float4 i0 = Sp[0], i1 = Sp[1], i2 = Sp[2], i3 = Sp[3];
    ull s_0, s_1, s_2, s_3, s_4, s_5, s_6, s_7;
    PK2(s_0, i0.x, i0.y); PK2(s_1, i0.z, i0.w);
    PK2(s_2, i1.x, i1.y); PK2(s_3, i1.z, i1.w);
    PK2(s_4, i2.x, i2.y); PK2(s_5, i2.z, i2.w);
    PK2(s_6, i3.x, i3.y); PK2(s_7, i3.z, i3.w);

    const size_t base = (size_t)b * DD + h * 64;
    const float* qb = g_proj + base;
    const float* kb = g_proj + (size_t)SEGC + base;
    const float* vb = g_proj + 2ull * SEGC + base;
    const size_t ob = (size_t)b * DD + h * 64 + d;

    float4 kr0_0, kr0_1, kr0_2, kr0_3, qr0_0, qr0_1, qr0_2, qr0_3;
    float4 kr1_0, kr1_1, kr1_2, kr1_3, qr1_0, qr1_1, qr1_2, qr1_3;
    float4 kr2_0, kr2_1, kr2_2, kr2_3, qr2_0, qr2_1, qr2_2, qr2_3;
    float4 kr3_0, kr3_1, kr3_2, kr3_3, qr3_0, qr3_1, qr3_2, qr3_3;
    float vr0, ar0, br0, vr1, ar1, br1, vr2, ar2, br2, vr3, ar3, br3;

    LOADS(0, 0); LOADS(1, 1); LOADS(2, 2); LOADS(3, 3);

    for (int t = 0; t < TT; t += 4) {
        STEP(0, t);
        STEP(1, t + 1);
        STEP(2, t + 2);
        STEP(3, t + 3);
    }

    float4 f0, f1, f2, f3;
    UNPK2(f0.x, f0.y, s_0); UNPK2(f0.z, f0.w, s_1);
    UNPK2(f1.x, f1.y, s_2); UNPK2(f1.z, f1.w, s_3);
    UNPK2(f2.x, f2.y, s_4); UNPK2(f2.z, f2.w, s_5);
    UNPK2(f3.x, f3.y, s_6); UNPK2(f3.z, f3.w, s_7);
    float4* So = (float4*)(out + (size_t)(TT * BB * DD) + ((size_t)bh * 64 + d) * 64 + qu * 16);
    So[0] = f0; So[1] = f1; So[2] = f2; So[3] = f3;
}

// =====================================================================
extern "C" void kernel_launch(void* const* d_in, const int* in_sizes, int n_in,
                              void* d_out, int out_size)
{
    const float* x  = (const float*)d_in[0];
    const float* S0 = (const float*)d_in[1];
    const float* Wq = (const float*)d_in[2];
    const float* Wk = (const float*)d_in[3];
    const float* Wv = (const float*)d_in[4];
    const float* Wa = (const float*)d_in[5];
    const float* ba = (const float*)d_in[6];
    const float* Wb = (const float*)d_in[7];
    const float* bb = (const float*)d_in[8];
    float* out = (float*)d_out;

    cudaFuncSetAttribute(gemm_mma, cudaFuncAttributeMaxDynamicSharedMemorySize, 3 * STG);

    knop<<<1, 32>>>();                 // slot shifters: 4th launch = gemm_mma
    knop<<<1, 32>>>();
    pack_all<<<6656, 256>>>(x, Wq, Wk, Wv, Wa, Wb);
    gemm_mma<<<2560, 128, 3 * STG>>>();
    postproc<<<16384, 256>>>(ba, bb);
    scan<<<BB * HH, 256>>>(S0, out);
}

// round 13
// speedup vs baseline: 1.2253x; 1.2253x over previous
#include <cuda_runtime.h>
#include <cuda_bf16.h>
#include <cstdint>

// ---------------- problem dims ----------------
#define TT 1024
#define BB 8
#define DD 1024
#define HH 16
#define ROWS 8192
#define SEGC 8388608u
#define KC 3072                 // concatenated split-bf16 K (hi|hi|lo vs hi|lo|hi)

typedef unsigned long long ull;

// ---------------- device scratch ----------------
__device__ float g_proj[5ull * SEGC];     // q,k,v,apre,bpre (fp32)
__device__ float g_alpha[ROWS * HH];
__device__ float g_beta[ROWS * HH];
__device__ __align__(16) __nv_bfloat16 g_xcat[(size_t)ROWS * KC];   // 48 MB
__device__ __align__(16) __nv_bfloat16 g_wcat[(size_t)5120 * KC];   // 30 MB

// ---------------- helpers ----------------
__device__ __forceinline__ uint32_t smem_u32(const void* p) {
    uint32_t a;
    asm("{ .reg .u64 t; cvta.to.shared.u64 t, %1; cvt.u32.u64 %0, t; }" : "=r"(a) : "l"(p));
    return a;
}
__device__ __forceinline__ void cpa16(uint32_t dst, const void* src) {
    asm volatile("cp.async.cg.shared.global [%0], [%1], 16;" :: "r"(dst), "l"(src));
}
#define CP_COMMIT() asm volatile("cp.async.commit_group;")
#define CP_WAIT2()  asm volatile("cp.async.wait_group 2;")

__device__ __forceinline__ void ldm4(uint32_t* r, uint32_t a) {
    asm volatile("ldmatrix.sync.aligned.m8n8.x4.shared.b16 {%0,%1,%2,%3}, [%4];"
        : "=r"(r[0]), "=r"(r[1]), "=r"(r[2]), "=r"(r[3]) : "r"(a));
}
__device__ __forceinline__ void mma16816(float* d, const uint32_t* a, uint32_t b0, uint32_t b1) {
    asm volatile(
        "mma.sync.aligned.m16n8k16.row.col.f32.bf16.bf16.f32 "
        "{%0,%1,%2,%3},{%4,%5,%6,%7},{%8,%9},{%0,%1,%2,%3};"
        : "+f"(d[0]), "+f"(d[1]), "+f"(d[2]), "+f"(d[3])
        : "r"(a[0]), "r"(a[1]), "r"(a[2]), "r"(a[3]), "r"(b0), "r"(b1));
}

// packed f32x2 (sm_100+ FFMA2)
#define FMA2(d, a, b, c) asm("fma.rn.f32x2 %0, %1, %2, %3;" : "=l"(d) : "l"(a), "l"(b), "l"(c))
#define MUL2(d, a, b)    asm("mul.rn.f32x2 %0, %1, %2;"     : "=l"(d) : "l"(a), "l"(b))
#define PK2(d, x, y)     asm("mov.b64 %0, {%1, %2};"        : "=l"(d) : "f"(x), "f"(y))
#define UNPK2(x, y, d)   asm("mov.b64 {%0, %1}, %2;"        : "=f"(x), "=f"(y) : "l"(d))

// split one float into bf16 hi + bf16 lo
__device__ __forceinline__ void split2(float f0, float f1, uint32_t& hw, uint32_t& lw) {
    __nv_bfloat16 h0 = __float2bfloat16(f0);
    __nv_bfloat16 h1 = __float2bfloat16(f1);
    __nv_bfloat16 l0 = __float2bfloat16(f0 - __bfloat162float(h0));
    __nv_bfloat16 l1 = __float2bfloat16(f1 - __bfloat162float(h1));
    hw = (uint32_t)__bfloat16_as_ushort(h0) | ((uint32_t)__bfloat16_as_ushort(h1) << 16);
    lw = (uint32_t)__bfloat16_as_ushort(l0) | ((uint32_t)__bfloat16_as_ushort(l1) << 16);
}

// =====================================================================
// pack_all: fused pack_x + pack_w.
// =====================================================================
__global__ __launch_bounds__(256)
void pack_all(const float* __restrict__ x,
              const float* __restrict__ W0, const float* __restrict__ W1,
              const float* __restrict__ W2, const float* __restrict__ W3,
              const float* __restrict__ W4)
{
    unsigned idx = blockIdx.x * 256 + threadIdx.x;
    if (idx < 1048576u) {
        unsigned e = idx * 8;
        unsigned row = e >> 10, col = e & 1023;
        float4 f0 = *(const float4*)(x + e);
        float4 f1 = *(const float4*)(x + e + 4);
        uint4 hi, lo;
        split2(f0.x, f0.y, hi.x, lo.x);
        split2(f0.z, f0.w, hi.y, lo.y);
        split2(f1.x, f1.y, hi.z, lo.z);
        split2(f1.z, f1.w, hi.w, lo.w);
        __nv_bfloat16* base = g_xcat + (size_t)row * KC;
        *(uint4*)(base + col)        = hi;
        *(uint4*)(base + col + 1024) = hi;
        *(uint4*)(base + col + 2048) = lo;
    } else {
        unsigned j = idx - 1048576u;
        unsigned e = j * 8;
        unsigned seg = e >> 20;
        unsigned n = (e >> 10) & 1023, k = e & 1023;
        const float* W = (seg == 0) ? W0 : (seg == 1) ? W1 : (seg == 2) ? W2
                         : (seg == 3) ? W3 : W4;
        const float* src = W + (size_t)n * 1024 + k;
        float4 f0 = *(const float4*)(src);
        float4 f1 = *(const float4*)(src + 4);
        uint4 hi, lo;
        split2(f0.x, f0.y, hi.x, lo.x);
        split2(f0.z, f0.w, hi.y, lo.y);
        split2(f1.x, f1.y, hi.z, lo.z);
        split2(f1.z, f1.w, hi.w, lo.w);
        __nv_bfloat16* base = g_wcat + (size_t)(seg * 1024 + n) * KC;
        *(uint4*)(base + k)        = hi;
        *(uint4*)(base + k + 1024) = lo;
        *(uint4*)(base + k + 2048) = hi;
    }
}

// =====================================================================
// gemm_mma: EXACT R8 config (best measured: 752.9us, tensor 56.6%).
// BM=BN=128, BK=32, 4-stage cp.async ring (3 in flight), 8 warps,
// warp tile 64x32, 2 CTAs/SM. 80B-padded rows -> conflict-free ldmatrix.
// =====================================================================
#define STG 20480

__global__ __launch_bounds__(256, 2)
void gemm_mma()
{
    extern __shared__ __align__(16) unsigned char sm[];
    const uint32_t smb = smem_u32(sm);

    const int bid = blockIdx.x;
    const int mt = bid / 40, nt = bid % 40;
    const int tid = threadIdx.x;
    const int lane = tid & 31, wid = tid >> 5;
    const int wm = wid & 1, wn = wid >> 1;

    const int lrow = tid >> 2, lch = tid & 3;
    const __nv_bfloat16* Ag = g_xcat + (size_t)(mt * 128 + lrow) * KC + lch * 8;
    const __nv_bfloat16* Bg = g_wcat + (size_t)(nt * 128 + lrow) * KC + lch * 8;
    const uint32_t sA = smb + lrow * 80 + lch * 16;
    const uint32_t sB = smb + 10240 + lrow * 80 + lch * 16;

    auto load = [&](int it, int stage) {
        const uint32_t off = stage * STG;
        const __nv_bfloat16* ag = Ag + it * 32;
        const __nv_bfloat16* bg = Bg + it * 32;
        cpa16(sA + off,           ag);
        cpa16(sA + off + 64 * 80, ag + (size_t)64 * KC);
        cpa16(sB + off,           bg);
        cpa16(sB + off + 64 * 80, bg + (size_t)64 * KC);
    };

    uint32_t aAddr[4], bAddr[2];
#pragma unroll
    for (int f = 0; f < 4; f++)
        aAddr[f] = smb + (wm * 64 + f * 16 + (lane & 15)) * 80 + (lane >> 4) * 16;
#pragma unroll
    for (int x = 0; x < 2; x++)
        bAddr[x] = smb + 10240 + (wn * 32 + x * 16 + (lane & 15)) * 80 + (lane >> 4) * 16;

    float acc[4][4][4];
#pragma unroll
    for (int f = 0; f < 4; f++)
#pragma unroll
        for (int g = 0; g < 4; g++)
#pragma unroll
            for (int i = 0; i < 4; i++) acc[f][g][i] = 0.f;

    load(0, 0); CP_COMMIT();
    load(1, 1); CP_COMMIT();
    load(2, 2); CP_COMMIT();

    const int NIT = KC / 32;    // 96
    for (int it = 0; it < NIT; it++) {
        CP_WAIT2();
        __syncthreads();
        if (it + 3 < NIT) load(it + 3, (it + 3) & 3);
        CP_COMMIT();

        const uint32_t st = (it & 3) * STG;
#pragma unroll
        for (int ks = 0; ks < 2; ks++) {
            uint32_t af[4][4], bf[2][4];
#pragma unroll
            for (int f = 0; f < 4; f++) ldm4(af[f], aAddr[f] + st + ks * 32);
#pragma unroll
            for (int x = 0; x < 2; x++) ldm4(bf[x], bAddr[x] + st + ks * 32);
#pragma unroll
            for (int f = 0; f < 4; f++) {
#pragma unroll
                for (int g = 0; g < 4; g++) {
                    const uint32_t b0 = bf[g >> 1][g & 1];
                    const uint32_t b1 = bf[g >> 1][(g & 1) + 2];
                    mma16816(acc[f][g], af[f], b0, b1);
                }
            }
        }
    }

    const int seg = nt >> 3;
    float* op = g_proj + (size_t)seg * SEGC;
    const int rbase = mt * 128 + wm * 64 + (lane >> 2);
    const int cbase = (nt & 7) * 128 + wn * 32 + (lane & 3) * 2;
#pragma unroll
    for (int f = 0; f < 4; f++) {
#pragma unroll
        for (int g = 0; g < 4; g++) {
            const int r = rbase + f * 16;
            const int c = cbase + g * 8;
            float2 v0 = make_float2(acc[f][g][0], acc[f][g][1]);
            float2 v1 = make_float2(acc[f][g][2], acc[f][g][3]);
            *(float2*)(op + (size_t)r * 1024 + c)       = v0;
            *(float2*)(op + (size_t)(r + 8) * 1024 + c) = v1;
        }
    }
}

// =====================================================================
// postproc: unchanged.
// =====================================================================
__device__ __forceinline__ float sigf(float x) { return 1.0f / (1.0f + expf(-x)); }

__global__ __launch_bounds__(256)
void postproc(const float* __restrict__ b_alpha, const float* __restrict__ b_beta)
{
    const int wid = threadIdx.x >> 5;
    const int lane = threadIdx.x & 31;
    const int gb = blockIdx.x * 8 + wid;   // tb*16 + h
    const int h = gb & 15;
    const size_t row = (size_t)(gb >> 4) * DD + h * 64 + lane * 2;

    float2 q  = *(float2*)(g_proj + row);
    float2 k  = *(float2*)(g_proj + (size_t)SEGC + row);
    float2 ap = *(float2*)(g_proj + 3ull * SEGC + row);
    float2 bp = *(float2*)(g_proj + 4ull * SEGC + row);
    float2 ba = *(const float2*)(b_alpha + h * 64 + lane * 2);
    float2 bbv = *(const float2*)(b_beta + h * 64 + lane * 2);

    float sq = fmaf(q.x, q.x, q.y * q.y);
    float sk = fmaf(k.x, k.x, k.y * k.y);
    float sa = sigf(ap.x + ba.x) + sigf(ap.y + ba.y);
    float sb = sigf(bp.x + bbv.x) + sigf(bp.y + bbv.y);
#pragma unroll
    for (int m = 16; m; m >>= 1) {
        sq += __shfl_xor_sync(0xffffffffu, sq, m);
        sk += __shfl_xor_sync(0xffffffffu, sk, m);
        sa += __shfl_xor_sync(0xffffffffu, sa, m);
        sb += __shfl_xor_sync(0xffffffffu, sb, m);
    }
    const float qi = 1.0f / fmaxf(sqrtf(sq), 1e-12f);
    const float ki = 1.0f / fmaxf(sqrtf(sk), 1e-12f);
    q.x *= qi; q.y *= qi;
    k.x *= ki; k.y *= ki;
    *(float2*)(g_proj + row) = q;
    *(float2*)(g_proj + (size_t)SEGC + row) = k;
    if (lane == 0) {
        g_alpha[gb] = sa * (1.0f / 64.0f);
        g_beta[gb]  = sb * (1.0f / 64.0f);
    }
}

// =====================================================================
// scan v6: v2 per-thread code, rows split 2-way across CTAs.
// Rows of S are independent (couple only via shared read-only k,q,a,b),
// so grid = 256 (bh x half), block = 128 (32 rows x 4 col-quarters).
// Identical arithmetic per row -> bitwise-same results as v2.
// =====================================================================
#define LOADS(S, t) { \
    const float4* kp = (const float4*)(kb + (size_t)(t) * 8192) + (qu * 4); \
    kr##S##_0 = kp[0]; kr##S##_1 = kp[1]; kr##S##_2 = kp[2]; kr##S##_3 = kp[3]; \
    const float4* qp = (const float4*)(qb + (size_t)(t) * 8192) + (qu * 4); \
    qr##S##_0 = qp[0]; qr##S##_1 = qp[1]; qr##S##_2 = qp[2]; qr##S##_3 = qp[3]; \
    vr##S = vb[(size_t)(t) * 8192 + d]; \
    ar##S = g_alpha[(t) * 128 + bh]; \
    br##S = g_beta[(t) * 128 + bh]; }

#define STEP(S, tt) { \
    const float a = ar##S, be = br##S, vv = vr##S; \
    ull K0,K1,K2,K3,K4,K5,K6,K7, Q0,Q1,Q2,Q3,Q4,Q5,Q6,Q7; \
    PK2(K0, kr##S##_0.x, kr##S##_0.y); PK2(K1, kr##S##_0.z, kr##S##_0.w); \
    PK2(K2, kr##S##_1.x, kr##S##_1.y); PK2(K3, kr##S##_1.z, kr##S##_1.w); \
    PK2(K4, kr##S##_2.x, kr##S##_2.y); PK2(K5, kr##S##_2.z, kr##S##_2.w); \
    PK2(K6, kr##S##_3.x, kr##S##_3.y); PK2(K7, kr##S##_3.z, kr##S##_3.w); \
    PK2(Q0, qr##S##_0.x, qr##S##_0.y); PK2(Q1, qr##S##_0.z, qr##S##_0.w); \
    PK2(Q2, qr##S##_1.x, qr##S##_1.y); PK2(Q3, qr##S##_1.z, qr##S##_1.w); \
    PK2(Q4, qr##S##_2.x, qr##S##_2.y); PK2(Q5, qr##S##_2.z, qr##S##_2.w); \
    PK2(Q6, qr##S##_3.x, qr##S##_3.y); PK2(Q7, qr##S##_3.z, qr##S##_3.w); \
    ull d0, d1; \
    MUL2(d0, s_0, K0); MUL2(d1, s_1, K1); \
    FMA2(d0, s_2, K2, d0); FMA2(d1, s_3, K3, d1); \
    FMA2(d0, s_4, K4, d0); FMA2(d1, s_5, K5, d1); \
    FMA2(d0, s_6, K6, d0); FMA2(d1, s_7, K7, d1); \
    float dx, dy, ex, ey; UNPK2(dx, dy, d0); UNPK2(ex, ey, d1); \
    float sk = (dx + ex) + (dy + ey); \
    sk += __shfl_xor_sync(0xffffffffu, sk, 1); \
    sk += __shfl_xor_sync(0xffffffffu, sk, 2); \
    const float coef = be * fmaf(-a, sk, vv); \
    ull a2, c2; PK2(a2, a, a); PK2(c2, coef, coef); \
    ull o0, o1, tmp; \
    MUL2(tmp, a2, s_0); FMA2(s_0, c2, K0, tmp); MUL2(o0, s_0, Q0); \
    MUL2(tmp, a2, s_1); FMA2(s_1, c2, K1, tmp); MUL2(o1, s_1, Q1); \
    MUL2(tmp, a2, s_2); FMA2(s_2, c2, K2, tmp); FMA2(o0, s_2, Q2, o0); \
    MUL2(tmp, a2, s_3); FMA2(s_3, c2, K3, tmp); FMA2(o1, s_3, Q3, o1); \
    MUL2(tmp, a2, s_4); FMA2(s_4, c2, K4, tmp); FMA2(o0, s_4, Q4, o0); \
    MUL2(tmp, a2, s_5); FMA2(s_5, c2, K5, tmp); FMA2(o1, s_5, Q5, o1); \
    MUL2(tmp, a2, s_6); FMA2(s_6, c2, K6, tmp); FMA2(o0, s_6, Q6, o0); \
    MUL2(tmp, a2, s_7); FMA2(s_7, c2, K7, tmp); FMA2(o1, s_7, Q7, o1); \
    float ox, oy, px, py; UNPK2(ox, oy, o0); UNPK2(px, py, o1); \
    float oo = (ox + px) + (oy + py); \
    oo += __shfl_xor_sync(0xffffffffu, oo, 1); \
    oo += __shfl_xor_sync(0xffffffffu, oo, 2); \
    if (qu == 0) out[(size_t)(tt) * 8192 + ob] = oo; \
    if ((tt) + 4 < TT) LOADS(S, (tt) + 4); }

__global__ __launch_bounds__(128, 1)
void scan(const float* __restrict__ S0, float* __restrict__ out)
{
    const int blk = blockIdx.x;
    const int bh = blk >> 1;               // (b,h) chain
    const int half = blk & 1;              // row half: [0,32) or [32,64)
    const int b = bh >> 4, h = bh & 15;
    const int tid = threadIdx.x;
    const int d = half * 32 + (tid >> 2);  // global row 0..63
    const int qu = tid & 3;

    const float4* Sp = (const float4*)(S0 + ((size_t)bh * 64 + d) * 64 + qu * 16);
    float4 i0 = Sp[0], i1 = Sp[1], i2 = Sp[2], i3 = Sp[3];
    ull s_0, s_1, s_2, s_3, s_4, s_5, s_6, s_7;
    PK2(s_0, i0.x, i0.y); PK2(s_1, i0.z, i0.w);
    PK2(s_2, i1.x, i1.y); PK2(s_3, i1.z, i1.w);
    PK2(s_4, i2.x, i2.y); PK2(s_5, i2.z, i2.w);
    PK2(s_6, i3.x, i3.y); PK2(s_7, i3.z, i3.w);

    const size_t base = (size_t)b * DD + h * 64;
    const float* qb = g_proj + base;
    const float* kb = g_proj + (size_t)SEGC + base;
    const float* vb = g_proj + 2ull * SEGC + base;
    const size_t ob = (size_t)b * DD + h * 64 + d;

    float4 kr0_0, kr0_1, kr0_2, kr0_3, qr0_0, qr0_1, qr0_2, qr0_3;
    float4 kr1_0, kr1_1, kr1_2, kr1_3, qr1_0, qr1_1, qr1_2, qr1_3;
    float4 kr2_0, kr2_1, kr2_2, kr2_3, qr2_0, qr2_1, qr2_2, qr2_3;
    float4 kr3_0, kr3_1, kr3_2, kr3_3, qr3_0, qr3_1, qr3_2, qr3_3;
    float vr0, ar0, br0, vr1, ar1, br1, vr2, ar2, br2, vr3, ar3, br3;

    LOADS(0, 0); LOADS(1, 1); LOADS(2, 2); LOADS(3, 3);

    for (int t = 0; t < TT; t += 4) {
        STEP(0, t);
        STEP(1, t + 1);
        STEP(2, t + 2);
        STEP(3, t + 3);
    }

    float4 f0, f1, f2, f3;
    UNPK2(f0.x, f0.y, s_0); UNPK2(f0.z, f0.w, s_1);
    UNPK2(f1.x, f1.y, s_2); UNPK2(f1.z, f1.w, s_3);
    UNPK2(f2.x, f2.y, s_4); UNPK2(f2.z, f2.w, s_5);
    UNPK2(f3.x, f3.y, s_6); UNPK2(f3.z, f3.w, s_7);
    float4* So = (float4*)(out + (size_t)(TT * BB * DD) + ((size_t)bh * 64 + d) * 64 + qu * 16);
    So[0] = f0; So[1] = f1; So[2] = f2; So[3] = f3;
}

// =====================================================================
extern "C" void kernel_launch(void* const* d_in, const int* in_sizes, int n_in,
                              void* d_out, int out_size)
{
    const float* x  = (const float*)d_in[0];
    const float* S0 = (const float*)d_in[1];
    const float* Wq = (const float*)d_in[2];
    const float* Wk = (const float*)d_in[3];
    const float* Wv = (const float*)d_in[4];
    const float* Wa = (const float*)d_in[5];
    const float* ba = (const float*)d_in[6];
    const float* Wb = (const float*)d_in[7];
    const float* bb = (const float*)d_in[8];
    float* out = (float*)d_out;

    cudaFuncSetAttribute(gemm_mma, cudaFuncAttributeMaxDynamicSharedMemorySize, 4 * STG);

    pack_all<<<6656, 256>>>(x, Wq, Wk, Wv, Wa, Wb);
    gemm_mma<<<2560, 256, 4 * STG>>>();
    postproc<<<16384, 256>>>(ba, bb);
    scan<<<256, 128>>>(S0, out);       // 4th launch -> ncu capture slot
}